// round 3
// baseline (speedup 1.0000x reference)
#include <cuda_runtime.h>
#include <cstdint>

#define BB 64
#define HH 1024
#define WW 1024
#define NN 256
#define MAX_ITERS 20
#define W9 (1.0f/9.0f)
#define TP 17          // smem tile pitch (15-wide rows, conflict-scrambling)

// scratch
__device__ int g_end[BB * NN * 2];   // end coords after gravity (x,y)
__device__ int g_meta[BB * NN];      // winner | leader<<8 | has<<16

// ---------------------------------------------------------------------------
// Kernel 1: gravity_move, one warp per point. 15x15 raw tile per global
// round trip => >=2 hill-climb iterations per load, all from SMEM.
// ---------------------------------------------------------------------------
__global__ void __launch_bounds__(256) gravity_kernel(
    const float* __restrict__ depth, const int* __restrict__ points)
{
    const int w    = threadIdx.x >> 5;
    const int lane = threadIdx.x & 31;
    const int pidx = blockIdx.x * 8 + w;          // grid = B*N/8
    const int b    = pidx >> 8;                   // N = 256
    const float* dep = depth + (size_t)b * HH * WW;

    int px = points[pidx * 2 + 0];
    int py = points[pidx * 2 + 1];

    __shared__ float tile[8][15 * TP + 1];
    float* T = &tile[w][0];

    // ---- loop-invariant per-lane candidate constants (cells 0..48) ----
    const int cA  = lane;
    const int rA  = cA / 7;
    const int dyA = rA - 3,  dxA = cA - rA * 7 - 3;
    const int cB  = lane + 32;
    const int rB  = cB / 7;
    const int dyB = rB - 3,  dxB = cB - rB * 7 - 3;
    const bool hasB = (cB < 49);
    // top-left of the candidate's 3x3 window inside the 15x15 tile, relative
    // to (pos-center) offset: ((dy+6) rows, (dx+6) cols)
    const int sA = (dyA + 6) * TP + (dxA + 6);
    const int sB = (dyB + 6) * TP + (dxB + 6);

    int it = 0;
    bool done = false;

    while (!done && it < MAX_ITERS) {
        // warp-uniform branch (px,py identical across lanes)
        const bool interior = (px >= 7) & (px <= WW - 8) &
                              (py >= 7) & (py <= HH - 8);

        if (interior) {
            const int cy = py, cx = px;
            const float* base = dep + (cy - 7) * WW + (cx - 7);
            __syncwarp();
            #pragma unroll
            for (int k = 0; k < 8; ++k) {
                int e = lane + 32 * k;
                if (k < 7 || e < 225) {
                    int r = e / 15, c = e - r * 15;
                    T[r * TP + c] = __ldg(base + r * WW + c);
                }
            }
            __syncwarp();

            // iterate inside the tile while |pos-center|inf <= 3
            while (true) {
                const int off = (py - cy) * TP + (px - cx);

                const float* p = T + off + sA;
                float bestv = 0.0f;
                #pragma unroll
                for (int i2 = 0; i2 < 3; ++i2)
                    #pragma unroll
                    for (int j2 = 0; j2 < 3; ++j2)
                        bestv = fmaf(p[i2 * TP + j2], W9, bestv);
                int besti = cA;

                if (hasB) {
                    const float* q = T + off + sB;
                    float a2 = 0.0f;
                    #pragma unroll
                    for (int i2 = 0; i2 < 3; ++i2)
                        #pragma unroll
                        for (int j2 = 0; j2 < 3; ++j2)
                            a2 = fmaf(q[i2 * TP + j2], W9, a2);
                    if (a2 > bestv) { bestv = a2; besti = cB; }  // tie keeps cA
                }

                // warp argmax, first-index tie-break (matches jnp.argmax)
                #pragma unroll
                for (int o = 16; o; o >>= 1) {
                    float vo = __shfl_xor_sync(0xffffffffu, bestv, o);
                    int   io = __shfl_xor_sync(0xffffffffu, besti, o);
                    if (vo > bestv || (vo == bestv && io < besti)) { bestv = vo; besti = io; }
                }

                int rr = besti / 7;
                int ny = py + rr - 3;                 // no clip needed: in [1,1022]
                int nx = px + besti - rr * 7 - 3;
                bool moved = (nx != px) | (ny != py);
                px = nx; py = ny; ++it;

                if (!moved)          { done = true; break; }
                if (it >= MAX_ITERS) { done = true; break; }
                if (px < cx - 3 || px > cx + 3 ||
                    py < cy - 3 || py > cy + 3) break;    // need fresh tile
            }
        } else {
            // ---- border path: guarded 9x9 load (pitch 12), clipped cands ----
            const int by = py - 4, bx = px - 4;
            __syncwarp();
            {
                int r = lane / 9, c = lane - r * 9;
                int gy = by + r, gx = bx + c;
                T[r * 12 + c] = (gy >= 0 && gy < HH && gx >= 0 && gx < WW)
                                    ? __ldg(dep + gy * WW + gx) : 0.0f;
            }
            {
                int e = lane + 32;
                int r = e / 9, c = e - r * 9;
                int gy = by + r, gx = bx + c;
                T[r * 12 + c] = (gy >= 0 && gy < HH && gx >= 0 && gx < WW)
                                    ? __ldg(dep + gy * WW + gx) : 0.0f;
            }
            if (lane < 17) {
                int e = lane + 64;
                int r = e / 9, c = e - r * 9;
                int gy = by + r, gx = bx + c;
                T[r * 12 + c] = (gy >= 0 && gy < HH && gx >= 0 && gx < WW)
                                    ? __ldg(dep + gy * WW + gx) : 0.0f;
            }
            __syncwarp();

            float bestv;
            int   besti;
            {
                int yc = min(max(py + dyA, 0), HH - 1);
                int xc = min(max(px + dxA, 0), WW - 1);
                const float* p = T + (yc - by - 1) * 12 + (xc - bx - 1);
                float acc = 0.0f;
                #pragma unroll
                for (int i2 = 0; i2 < 3; ++i2)
                    #pragma unroll
                    for (int j2 = 0; j2 < 3; ++j2)
                        acc = fmaf(p[i2 * 12 + j2], W9, acc);
                bestv = acc; besti = cA;
            }
            if (hasB) {
                int yc = min(max(py + dyB, 0), HH - 1);
                int xc = min(max(px + dxB, 0), WW - 1);
                const float* q = T + (yc - by - 1) * 12 + (xc - bx - 1);
                float a2 = 0.0f;
                #pragma unroll
                for (int i2 = 0; i2 < 3; ++i2)
                    #pragma unroll
                    for (int j2 = 0; j2 < 3; ++j2)
                        a2 = fmaf(q[i2 * 12 + j2], W9, a2);
                if (a2 > bestv) { bestv = a2; besti = cB; }
            }

            #pragma unroll
            for (int o = 16; o; o >>= 1) {
                float vo = __shfl_xor_sync(0xffffffffu, bestv, o);
                int   io = __shfl_xor_sync(0xffffffffu, besti, o);
                if (vo > bestv || (vo == bestv && io < besti)) { bestv = vo; besti = io; }
            }

            int rr = besti / 7;
            int ny = min(max(py + rr - 3, 0), HH - 1);
            int nx = min(max(px + besti - rr * 7 - 3, 0), WW - 1);
            bool moved = (nx != px) | (ny != py);
            px = nx; py = ny; ++it;
            if (!moved) done = true;
        }
    }

    if (lane == 0) {
        g_end[pidx * 2 + 0] = px;
        g_end[pidx * 2 + 1] = py;
    }
}

// ---------------------------------------------------------------------------
// Kernel 2: pairwise overlap stats, one warp per point (lane covers 8 j's).
// ---------------------------------------------------------------------------
__global__ void __launch_bounds__(256) pairwise_kernel(
    const int* __restrict__ points)
{
    const int w    = threadIdx.x >> 5;
    const int lane = threadIdx.x & 31;
    const int blkInBatch = blockIdx.x & 31;
    const int b    = blockIdx.x >> 5;
    const int base = b * NN;

    __shared__ int ex[NN], ey[NN], sx[NN], sy[NN];
    const int t = threadIdx.x;
    ex[t] = g_end[(base + t) * 2 + 0];
    ey[t] = g_end[(base + t) * 2 + 1];
    sx[t] = points[(base + t) * 2 + 0];
    sy[t] = points[(base + t) * 2 + 1];
    __syncthreads();

    const int i   = blkInBatch * 8 + w;
    const int exi = ex[i], eyi = ey[i];

    int cnt = 0, minlead = 0x7fffffff;
    int bestd = 0x7fffffff, bestj = 0x7fffffff;

    #pragma unroll
    for (int k = 0; k < 8; ++k) {
        int j   = lane + 32 * k;
        int ddx = exi - ex[j], ddy = eyi - ey[j];
        int de  = ddx * ddx + ddy * ddy;
        if (de < 4) {                             // dist < 2.0 <=> sq < 4
            cnt++;
            minlead = min(minlead, j);            // argmax(ov) = first True
            int sdx = sx[j] - exi, sdy = sy[j] - eyi;
            int sd  = sdx * sdx + sdy * sdy;
            if (sd < bestd || (sd == bestd && j < bestj)) { bestd = sd; bestj = j; }
        }
    }

    #pragma unroll
    for (int o = 16; o; o >>= 1) {
        cnt     += __shfl_xor_sync(0xffffffffu, cnt, o);
        minlead  = min(minlead, __shfl_xor_sync(0xffffffffu, minlead, o));
        int od   = __shfl_xor_sync(0xffffffffu, bestd, o);
        int oj   = __shfl_xor_sync(0xffffffffu, bestj, o);
        if (od < bestd || (od == bestd && oj < bestj)) { bestd = od; bestj = oj; }
    }

    if (lane == 0)
        g_meta[base + i] = bestj | (minlead << 8) | ((cnt > 1) << 16);
}

// ---------------------------------------------------------------------------
// Kernel 3: finalize coordinates + peak (exact row-major 3x3 fma chain).
// ---------------------------------------------------------------------------
__global__ void __launch_bounds__(128) finalize_kernel(
    const float* __restrict__ depth, const int* __restrict__ points,
    float* __restrict__ out)
{
    const int gid  = blockIdx.x * 128 + threadIdx.x;   // 0..16383
    const int b    = gid >> 8;
    const int base = b * NN;
    const int i    = gid & 255;

    const int meta   = g_meta[gid];
    const int leader = (meta >> 8) & 0xff;
    const bool has   = (meta >> 16) & 1;
    const int wol    = g_meta[base + leader] & 0xff;   // winner[leader]

    int fx, fy;
    if (has) {
        if (i == wol) {
            fx = g_end[(base + leader) * 2 + 0];
            fy = g_end[(base + leader) * 2 + 1];
        } else {
            fx = points[gid * 2 + 0];
            fy = points[gid * 2 + 1];
        }
    } else {
        fx = g_end[gid * 2 + 0];
        fy = g_end[gid * 2 + 1];
    }

    const float* dep = depth + (size_t)b * HH * WW;
    float acc = 0.0f;
    #pragma unroll
    for (int u = -1; u <= 1; ++u)
        #pragma unroll
        for (int v = -1; v <= 1; ++v) {
            int gy = fy + u, gx = fx + v;
            float val = (gy >= 0 && gy < HH && gx >= 0 && gx < WW)
                            ? __ldg(dep + gy * WW + gx) : 0.0f;
            acc = fmaf(val, W9, acc);
        }

    out[gid * 2 + 0] = (float)fx;
    out[gid * 2 + 1] = (float)fy;
    out[BB * NN * 2 + gid] = acc;
}

// ---------------------------------------------------------------------------
extern "C" void kernel_launch(void* const* d_in, const int* in_sizes, int n_in,
                              void* d_out, int out_size)
{
    const float* depth  = (const float*)d_in[0];   // (64,1,1024,1024) f32
    const int*   points = (const int*)d_in[1];     // (64,256,2) i32
    float* out = (float*)d_out;                    // end (B,N,2) ++ peak (B,N)

    gravity_kernel <<<(BB * NN) / 8, 256>>>(depth, points);
    pairwise_kernel<<<BB * 32,       256>>>(points);
    finalize_kernel<<<(BB * NN) / 128, 128>>>(depth, points, out);
}